// round 14
// baseline (speedup 1.0000x reference)
#include <cuda_runtime.h>
#include <cstdint>
#include <cstddef>

// Problem constants
constexpr int T   = 50;
constexpr int B   = 512;
constexpr int IN  = 784;
constexpr int H   = 800;
constexpr int OUT = 10;
constexpr int MROWS = T * B;        // 25600
constexpr int BH    = B * H;        // 409600
constexpr int BO    = B * OUT;      // 5120

constexpr int NSLICE = 5;           // 7-bit slices per fp32 (35 bits below row max)
constexpr int NPAIR  = 15;          // all (s,t) with s+t <= 4

#define BETA 0.95f

// Scratch (static device globals; no runtime allocation)
__device__ float  g_x1[(size_t)T * BH];                  // x @ W1^T   (82 MB)
__device__ float  g_z2[(size_t)T * BH];                  // spk1 @ W2^T(82 MB)
__device__ float  g_z3[(size_t)T * BO];                  // spk2 @ W3^T(1 MB)
__device__ int8_t g_sx[(size_t)NSLICE * MROWS * IN];     // x slices (100 MB)
__device__ int8_t g_sw[(size_t)NSLICE * H * IN];         // W1 slices (3 MB)
__device__ float  g_su[MROWS];                           // per-row scale 2^(e-6)
__device__ float  g_sv[H];

// ---------------------------------------------------------------------------
// Row slicing: for each row, m = max|x|, e = ilogb(m)+1; slice s holds
// rint(resid / 2^(e-6-7s)), |slice| <= 64; residual update via exact FMA.
// All steps exact in fp32 (power-of-2 scales; representable differences).
// ---------------------------------------------------------------------------
__global__ void __launch_bounds__(256)
slice_rows(const float* __restrict__ X, int8_t* __restrict__ S,
           float* __restrict__ scale, int cols, size_t plane)
{
    const int row = blockIdx.x;
    const int tid = threadIdx.x;
    const float* xr = X + (size_t)row * cols;

    __shared__ float red[256];
    float m = 0.f;
    for (int k = tid; k < cols; k += 256) m = fmaxf(m, fabsf(xr[k]));
    red[tid] = m;
    __syncthreads();
    for (int w = 128; w > 0; w >>= 1) {
        if (tid < w) red[tid] = fmaxf(red[tid], red[tid + w]);
        __syncthreads();
    }
    m = red[0];
    const int e = (m > 0.f) ? (ilogbf(m) + 1) : 0;
    if (tid == 0) scale[row] = ldexpf(1.f, e - 6);

    const float u0   = ldexpf(1.f, e - 6);
    const float inv0 = ldexpf(1.f, 6 - e);

    for (int k = tid; k < cols; k += 256) {
        float r  = xr[k];
        float uu = u0, ii = inv0;
#pragma unroll
        for (int s = 0; s < NSLICE; s++) {
            const float q = rintf(__fmul_rn(r, ii));   // |q| <= 64
            S[(size_t)s * plane + (size_t)row * cols + k] = (int8_t)(int)q;
            r  = __fmaf_rn(-q, uu, r);                 // exact residual
            uu = __fmul_rn(uu, 0.0078125f);            // * 2^-7 (exact)
            ii = __fmul_rn(ii, 128.f);
        }
    }
}

// ---------------------------------------------------------------------------
// Layer-1 EXACT-DOT GEMM via Ozaki int8 slices + dp4a.
// For each slice pair (s,t): G = sum_k sx_s * sw_t  (exact s32 via dp4a;
// |G| <= 784*64*64 < 2^24 so (float)G and the 2^-7(s+t) scale are exact).
// Pairs folded with Knuth TwoSum (s,c); final exact power-of-2 rescale.
// Result: correctly-rounded dot to ~2^-32 rel — same class as R9-R12 f64/Dot2.
// BM=128, BN=80, BK=16, 256 threads, 8x5 micro-tile.
// ---------------------------------------------------------------------------
__global__ void __launch_bounds__(256)
gemm1_ozaki(const int8_t* __restrict__ SX, const int8_t* __restrict__ SW,
            const float* __restrict__ su, const float* __restrict__ sv,
            float* __restrict__ C)
{
    __shared__ uint32_t As[4][132];   // [k-quad][row], each u32 = 4 int8 k-vals
    __shared__ uint32_t Bs[4][84];

    const int tid = threadIdx.x;
    const int tx  = tid & 15;         // n direction
    const int ty  = tid >> 4;         // m direction
    const int m0  = blockIdx.x * 128;
    const int n0  = blockIdx.y * 80;

    const int   PS[NPAIR] = {0, 0,1, 0,1,2, 0,1,2,3, 0,1,2,3,4};
    const int   PT[NPAIR] = {0, 1,0, 2,1,0, 3,2,1,0, 4,3,2,1,0};
    const float PW[NPAIR] = {
        1.f,
        0.0078125f, 0.0078125f,
        6.103515625e-5f, 6.103515625e-5f, 6.103515625e-5f,
        4.76837158203125e-7f, 4.76837158203125e-7f,
        4.76837158203125e-7f, 4.76837158203125e-7f,
        3.7252902984619140625e-9f, 3.7252902984619140625e-9f,
        3.7252902984619140625e-9f, 3.7252902984619140625e-9f,
        3.7252902984619140625e-9f };

    float s[8][5], c[8][5];
#pragma unroll
    for (int i = 0; i < 8; i++)
#pragma unroll
        for (int j = 0; j < 5; j++) { s[i][j] = 0.f; c[i][j] = 0.f; }

#pragma unroll 1
    for (int pidx = 0; pidx < NPAIR; pidx++) {
        const int8_t* Ap = SX + (size_t)PS[pidx] * ((size_t)MROWS * IN);
        const int8_t* Bp = SW + (size_t)PT[pidx] * ((size_t)H * IN);
        const float   wd = PW[pidx];

        int acc[8][5];
#pragma unroll
        for (int i = 0; i < 8; i++)
#pragma unroll
            for (int j = 0; j < 5; j++) acc[i][j] = 0;

#pragma unroll 1
        for (int k0 = 0; k0 < IN; k0 += 16) {
            if (tid < 128) {
                uint4 v = *reinterpret_cast<const uint4*>(
                    Ap + (size_t)(m0 + tid) * IN + k0);
                As[0][tid] = v.x; As[1][tid] = v.y;
                As[2][tid] = v.z; As[3][tid] = v.w;
            } else if (tid < 208) {
                const int col = tid - 128;
                uint4 v = *reinterpret_cast<const uint4*>(
                    Bp + (size_t)(n0 + col) * IN + k0);
                Bs[0][col] = v.x; Bs[1][col] = v.y;
                Bs[2][col] = v.z; Bs[3][col] = v.w;
            }
            __syncthreads();

#pragma unroll
            for (int q = 0; q < 4; q++) {
                int a[8], b[5];
#pragma unroll
                for (int i = 0; i < 8; i++) a[i] = (int)As[q][ty * 8 + i];
#pragma unroll
                for (int j = 0; j < 5; j++) b[j] = (int)Bs[q][tx * 5 + j];
#pragma unroll
                for (int i = 0; i < 8; i++)
#pragma unroll
                    for (int j = 0; j < 5; j++)
                        acc[i][j] = __dp4a(a[i], b[j], acc[i][j]);
            }
            __syncthreads();
        }

        // Fold this pair: term = 2^-7(s+t) * G  (exact), TwoSum into (s,c)
#pragma unroll
        for (int i = 0; i < 8; i++)
#pragma unroll
            for (int j = 0; j < 5; j++) {
                const float term = __fmul_rn((float)acc[i][j], wd);
                const float t   = __fadd_rn(s[i][j], term);
                const float bb  = __fsub_rn(t, s[i][j]);
                const float err = __fadd_rn(
                    __fsub_rn(s[i][j], __fsub_rn(t, bb)),
                    __fsub_rn(term, bb));
                s[i][j] = t;
                c[i][j] = __fadd_rn(c[i][j], err);
            }
    }

#pragma unroll
    for (int i = 0; i < 8; i++) {
        const int r = m0 + ty * 8 + i;
        const float ui = __ldg(su + r);
#pragma unroll
        for (int j = 0; j < 5; j++) {
            const int cc = n0 + tx * 5 + j;
            const float val = __fadd_rn(s[i][j], c[i][j]);   // rounds unscaled dot
            const float sc  = __fmul_rn(ui, __ldg(sv + cc)); // exact 2^k product
            C[(size_t)r * H + cc] = __fmul_rn(val, sc);      // exact scale
        }
    }
}

// ---------------------------------------------------------------------------
// SERIAL-FP32 GEMM (layer 2) — strict ascending-k fp32 FMA chain from 0 per
// output (bit-exact class, proven R9-R12). 8x10 micro-tile (BM=128, BN=160).
// ---------------------------------------------------------------------------
__global__ void __launch_bounds__(256)
gemm_nt_f32(const float* __restrict__ A, const float* __restrict__ Bw,
            float* __restrict__ C, int M, int N, int K)
{
    __shared__ float As[16][129];
    __shared__ float Bs[16][161];

    const int tid = threadIdx.x;
    const int tx  = tid & 15;
    const int ty  = tid >> 4;
    const int m0  = blockIdx.x * 128;
    const int n0  = blockIdx.y * 160;

    float acc[8][10];
#pragma unroll
    for (int i = 0; i < 8; i++)
#pragma unroll
        for (int j = 0; j < 10; j++) acc[i][j] = 0.f;

    for (int k0 = 0; k0 < K; k0 += 16) {
#pragma unroll
        for (int j = tid; j < 512; j += 256) {
            int row = j >> 2;
            int c4  = (j & 3) << 2;
            float4 v = *reinterpret_cast<const float4*>(
                A + (size_t)(m0 + row) * K + k0 + c4);
            As[c4 + 0][row] = v.x;
            As[c4 + 1][row] = v.y;
            As[c4 + 2][row] = v.z;
            As[c4 + 3][row] = v.w;
        }
#pragma unroll
        for (int j = tid; j < 640; j += 256) {
            int row = j >> 2;
            int c4  = (j & 3) << 2;
            float4 v = *reinterpret_cast<const float4*>(
                Bw + (size_t)(n0 + row) * K + k0 + c4);
            Bs[c4 + 0][row] = v.x;
            Bs[c4 + 1][row] = v.y;
            Bs[c4 + 2][row] = v.z;
            Bs[c4 + 3][row] = v.w;
        }
        __syncthreads();

#pragma unroll
        for (int kk = 0; kk < 16; kk++) {   // strict ascending-k chain
            float a[8], b[10];
#pragma unroll
            for (int i = 0; i < 8; i++) a[i] = As[kk][ty * 8 + i];
#pragma unroll
            for (int j = 0; j < 10; j++) b[j] = Bs[kk][tx * 10 + j];
#pragma unroll
            for (int i = 0; i < 8; i++)
#pragma unroll
                for (int j = 0; j < 10; j++)
                    acc[i][j] = fmaf(a[i], b[j], acc[i][j]);
        }
        __syncthreads();
    }

#pragma unroll
    for (int i = 0; i < 8; i++) {
        const int r = m0 + ty * 8 + i;
#pragma unroll
        for (int j = 0; j < 10; j++)
            C[(size_t)r * N + n0 + tx * 10 + j] = acc[i][j];
    }
}

// ---------------------------------------------------------------------------
// Skinny exact-dot GEMM (layer 3) via fp32 Dot2 — proven exact (R12).
// ---------------------------------------------------------------------------
__global__ void __launch_bounds__(640)
gemm3_df32(const float* __restrict__ A, const float* __restrict__ W3,
           float* __restrict__ Cz)
{
    __shared__ float As[64][81];
    const int tid  = threadIdx.x;
    const int r    = tid & 63;
    const int o    = tid >> 6;          // 0..9
    const int row0 = blockIdx.x * 64;

    float s = 0.f, c = 0.f;
    for (int k0 = 0; k0 < 800; k0 += 80) {
        for (int j = tid; j < 1280; j += 640) {
            int rr = j / 20;
            int cc = (j % 20) * 4;
            float4 v = *reinterpret_cast<const float4*>(
                A + (size_t)(row0 + rr) * 800 + k0 + cc);
            As[rr][cc + 0] = v.x;
            As[rr][cc + 1] = v.y;
            As[rr][cc + 2] = v.z;
            As[rr][cc + 3] = v.w;
        }
        __syncthreads();
        const float* w = W3 + (size_t)o * 800 + k0;
#pragma unroll
        for (int k = 0; k < 80; k++) {
            const float a = As[r][k];
            const float b = __ldg(w + k);
            const float p  = __fmul_rn(a, b);
            const float ep = __fmaf_rn(a, b, -p);
            const float t   = __fadd_rn(s, p);
            const float bb  = __fsub_rn(t, s);
            const float err = __fadd_rn(
                __fsub_rn(s, __fsub_rn(t, bb)),
                __fsub_rn(p, bb));
            s = t;
            c = __fadd_rn(c, __fadd_rn(err, ep));
        }
        __syncthreads();
    }
    Cz[(size_t)(row0 + r) * OUT + o] = __fadd_rn(s, c);
}

// ---------------------------------------------------------------------------
// LIF scans — EXACT associations proven in R9-R12 (rel_err = 0). Do not change.
// ---------------------------------------------------------------------------
template <int ORDER>
__global__ void __launch_bounds__(256)
scan_hidden(const float* __restrict__ z, const float* __restrict__ bias,
            const float* __restrict__ thr, float* __restrict__ spk_out)
{
    const int idx = blockIdx.x * blockDim.x + threadIdx.x;
    if (idx >= BH) return;
    const int h = idx % H;
    const float bv = bias[h];
    const float tv = thr[h];
    float m = 0.f;
#pragma unroll
    for (int t = 0; t < T; t++) {
        const float zv = z[(size_t)t * BH + idx];
        float mnew;
        if (ORDER == 1) {
            const float xt = __fadd_rn(zv, bv);
            mnew = __fadd_rn(__fmul_rn(BETA, m), xt);
        } else {
            mnew = __fadd_rn(__fadd_rn(__fmul_rn(BETA, m), zv), bv);
        }
        const bool fire = (mnew > tv);
        spk_out[(size_t)t * BH + idx] = fire ? 1.f : 0.f;
        m = fire ? 0.f : mnew;
    }
}

__global__ void __launch_bounds__(256)
scan_out(const float* __restrict__ z3, const float* __restrict__ b3,
         float* __restrict__ s3, float* __restrict__ sum_out)
{
    const int idx = blockIdx.x * blockDim.x + threadIdx.x;
    if (idx >= BO) return;
    const int o = idx % OUT;
    const float bv = b3[o];
    float m = 0.f, sum = 0.f;
#pragma unroll
    for (int t = 0; t < T; t++) {
        const float zv = z3[(size_t)t * BO + idx];
        const float mnew = __fadd_rn(__fadd_rn(__fmul_rn(BETA, m), zv), bv);
        const bool fire = (mnew > 1.0f);
        const float s = fire ? 1.f : 0.f;
        s3[(size_t)t * BO + idx] = s;
        sum = __fadd_rn(sum, s);
        m = fire ? 0.f : mnew;
    }
    sum_out[idx] = sum;
}

// ---------------------------------------------------------------------------
// kernel_launch — 8 graph-capturable launches, allocation-free.
// Inputs: x, W1, b1, W2, b2, W3, b3, thresh1, thresh2
// Outputs: sum[512,10], s1r[50,512,800], s2r[50,512,800], s3r[50,512,10]
// ---------------------------------------------------------------------------
extern "C" void kernel_launch(void* const* d_in, const int* in_sizes, int n_in,
                              void* d_out, int out_size)
{
    const float* x    = (const float*)d_in[0];
    const float* W1   = (const float*)d_in[1];
    const float* b1   = (const float*)d_in[2];
    const float* W2   = (const float*)d_in[3];
    const float* b2   = (const float*)d_in[4];
    const float* W3   = (const float*)d_in[5];
    const float* b3   = (const float*)d_in[6];
    const float* thr1 = (const float*)d_in[7];
    const float* thr2 = (const float*)d_in[8];

    float* out     = (float*)d_out;
    float* out_sum = out;                                  // [512,10]
    float* s1      = out + (size_t)BO;                     // [50,512,800]
    float* s2      = s1 + (size_t)T * BH;                  // [50,512,800]
    float* s3      = s2 + (size_t)T * BH;                  // [50,512,10]

    void *px1, *pz2, *pz3, *psx, *psw, *psu, *psv;
    cudaGetSymbolAddress(&px1, g_x1);
    cudaGetSymbolAddress(&pz2, g_z2);
    cudaGetSymbolAddress(&pz3, g_z3);
    cudaGetSymbolAddress(&psx, g_sx);
    cudaGetSymbolAddress(&psw, g_sw);
    cudaGetSymbolAddress(&psu, g_su);
    cudaGetSymbolAddress(&psv, g_sv);

    // 1) Slice x and W1 into 5 int8 planes each (exact splits)
    slice_rows<<<MROWS, 256>>>(x, (int8_t*)psx, (float*)psu, IN,
                               (size_t)MROWS * IN);
    slice_rows<<<H, 256>>>(W1, (int8_t*)psw, (float*)psv, IN,
                           (size_t)H * IN);

    // 2) x1 = exact-dot(x, W1^T) via dp4a Ozaki (15 slice pairs)
    {
        dim3 grid(MROWS / 128, H / 80);
        gemm1_ozaki<<<grid, 256>>>((const int8_t*)psx, (const int8_t*)psw,
                                   (const float*)psu, (const float*)psv,
                                   (float*)px1);
    }
    // 3) layer-1 LIF scan -> spk1  [bit-exact]
    scan_hidden<1><<<(BH + 255) / 256, 256>>>((const float*)px1, b1, thr1, s1);

    // 4) z2 = serial-fp32(spk1 @ W2^T)  [bit-exact]
    {
        dim3 grid(MROWS / 128, H / 160);
        gemm_nt_f32<<<grid, 256>>>(s1, W2, (float*)pz2, MROWS, H, H);
    }
    // 5) layer-2 LIF scan -> spk2  [bit-exact]
    scan_hidden<2><<<(BH + 255) / 256, 256>>>((const float*)pz2, b2, thr2, s2);

    // 6) z3 = exact-dot(spk2, W3^T) — fp32 Dot2
    gemm3_df32<<<MROWS / 64, 640>>>(s2, W3, (float*)pz3);

    // 7) layer-3 LIF scan -> s3r + spike-count sum
    scan_out<<<(BO + 255) / 256, 256>>>((const float*)pz3, b3, s3, out_sum);
}

// round 15
// speedup vs baseline: 1.7234x; 1.7234x over previous
#include <cuda_runtime.h>
#include <cstdint>
#include <cstddef>

// Problem constants
constexpr int T   = 50;
constexpr int B   = 512;
constexpr int IN  = 784;
constexpr int KPAD = 800;           // slices padded to 800 (25 x k32 chunks)
constexpr int H   = 800;
constexpr int OUT = 10;
constexpr int MROWS = T * B;        // 25600
constexpr int BH    = B * H;        // 409600
constexpr int BO    = B * OUT;      // 5120

constexpr int NSLICE = 5;           // 7-bit slices per fp32

#define BETA 0.95f

// Scratch (static device globals; no runtime allocation)
__device__ float  g_x1[(size_t)T * BH];                  // x @ W1^T   (82 MB)
__device__ float  g_z2[(size_t)T * BH];                  // spk1 @ W2^T(82 MB)
__device__ float  g_z3[(size_t)T * BO];                  // spk2 @ W3^T(1 MB)
__device__ int8_t g_sx[(size_t)NSLICE * MROWS * KPAD];   // x slices (102 MB)
__device__ int8_t g_sw[(size_t)NSLICE * H * KPAD];       // W1 slices (3.2 MB)
__device__ float  g_su[MROWS];                           // per-row scale 2^(e-6)
__device__ float  g_sv[H];

// ---------------------------------------------------------------------------
// Row slicing (R14-PROVEN exact): m = row max|x|, e = ilogb(m)+1; slice s =
// rint(resid / 2^(e-6-7s)), |slice| <= 64; exact FMA residual. K padded with
// zeros to KPAD so the GEMM can run uniform k32 chunks.
// ---------------------------------------------------------------------------
__global__ void __launch_bounds__(256)
slice_rows(const float* __restrict__ X, int8_t* __restrict__ S,
           float* __restrict__ scale, int cols, size_t plane)
{
    const int row = blockIdx.x;
    const int tid = threadIdx.x;
    const float* xr = X + (size_t)row * cols;

    __shared__ float red[256];
    float m = 0.f;
    for (int k = tid; k < cols; k += 256) m = fmaxf(m, fabsf(xr[k]));
    red[tid] = m;
    __syncthreads();
    for (int w = 128; w > 0; w >>= 1) {
        if (tid < w) red[tid] = fmaxf(red[tid], red[tid + w]);
        __syncthreads();
    }
    m = red[0];
    const int e = (m > 0.f) ? (ilogbf(m) + 1) : 0;
    if (tid == 0) scale[row] = ldexpf(1.f, e - 6);

    const float u0   = ldexpf(1.f, e - 6);
    const float inv0 = ldexpf(1.f, 6 - e);

    for (int k = tid; k < cols; k += 256) {
        float r  = xr[k];
        float uu = u0, ii = inv0;
#pragma unroll
        for (int s = 0; s < NSLICE; s++) {
            const float q = rintf(__fmul_rn(r, ii));   // |q| <= 64
            S[(size_t)s * plane + (size_t)row * KPAD + k] = (int8_t)(int)q;
            r  = __fmaf_rn(-q, uu, r);                 // exact residual
            uu = __fmul_rn(uu, 0.0078125f);            // * 2^-7 (exact)
            ii = __fmul_rn(ii, 128.f);
        }
    }
    // zero the K padding for all slices
    for (int k = cols + tid; k < KPAD; k += 256)
#pragma unroll
        for (int s = 0; s < NSLICE; s++)
            S[(size_t)s * plane + (size_t)row * KPAD + k] = 0;
}

// ---------------------------------------------------------------------------
// Layer-1 EXACT-DOT GEMM on TENSOR CORES: s8 mma.sync, exact s32 accumulate.
// Pairs (s,t) with equal d=s+t share one s32 accumulator (same 2^-7d scale);
// |G_d| <= 5*784*64^2 = 16.06M < 2^24 so (float)G_d is exact. Fold of the 5
// diagonal terms uses the R14-proven TwoSum; final power-of-2 rescale exact.
// Block 64x80, 8 warps (4x2), warp tile 16x40 (1 m-frag x 5 n-frags).
// ---------------------------------------------------------------------------
__device__ __forceinline__ void mma_s8(int* d, const uint32_t* a,
                                       const uint32_t* b)
{
    asm volatile(
        "mma.sync.aligned.m16n8k32.row.col.s32.s8.s8.s32 "
        "{%0,%1,%2,%3}, {%4,%5,%6,%7}, {%8,%9}, {%0,%1,%2,%3};"
        : "+r"(d[0]), "+r"(d[1]), "+r"(d[2]), "+r"(d[3])
        : "r"(a[0]), "r"(a[1]), "r"(a[2]), "r"(a[3]),
          "r"(b[0]), "r"(b[1]));
}

__global__ void __launch_bounds__(256)
gemm1_imma(const int8_t* __restrict__ SX, const int8_t* __restrict__ SW,
           const float* __restrict__ su, const float* __restrict__ sv,
           float* __restrict__ C)
{
    // smem tiles: [slice][row * 9 u32] — 32 k-bytes (8 u32) + 1 u32 pad
    __shared__ uint32_t As[NSLICE][64 * 9];
    __shared__ uint32_t Bs[NSLICE][80 * 9];

    const int tid  = threadIdx.x;
    const int warp = tid >> 5;
    const int lane = tid & 31;
    const int g    = lane >> 2;     // 0..7
    const int tg   = lane & 3;      // 0..3
    const int wm   = warp >> 1;     // 0..3  (16 rows each)
    const int wn   = warp & 1;      // 0..1  (40 cols each)
    const int m0   = blockIdx.x * 64;
    const int n0   = blockIdx.y * 80;

    int acc[NSLICE][5][4];          // [diagonal][n-frag][reg], exact s32
#pragma unroll
    for (int d = 0; d < NSLICE; d++)
#pragma unroll
        for (int nf = 0; nf < 5; nf++)
#pragma unroll
            for (int r = 0; r < 4; r++) acc[d][nf][r] = 0;

    for (int k0 = 0; k0 < KPAD; k0 += 32) {
        // Load A tiles: 5 slices x 64 rows x 2 uint4 = 640 uint4
#pragma unroll
        for (int idx = tid; idx < 640; idx += 256) {
            const int s   = idx >> 7;          // /128
            const int rem = idx & 127;
            const int row = rem >> 1;
            const int q   = rem & 1;
            uint4 v = *reinterpret_cast<const uint4*>(
                SX + (size_t)s * ((size_t)MROWS * KPAD)
                   + (size_t)(m0 + row) * KPAD + k0 + q * 16);
            uint32_t* dst = &As[s][row * 9 + q * 4];
            dst[0] = v.x; dst[1] = v.y; dst[2] = v.z; dst[3] = v.w;
        }
        // Load B tiles: 5 slices x 80 rows x 2 uint4 = 800 uint4
#pragma unroll
        for (int idx = tid; idx < 800; idx += 256) {
            const int s   = idx / 160;
            const int rem = idx - s * 160;
            const int row = rem >> 1;
            const int q   = rem & 1;
            uint4 v = *reinterpret_cast<const uint4*>(
                SW + (size_t)s * ((size_t)H * KPAD)
                   + (size_t)(n0 + row) * KPAD + k0 + q * 16);
            uint32_t* dst = &Bs[s][row * 9 + q * 4];
            dst[0] = v.x; dst[1] = v.y; dst[2] = v.z; dst[3] = v.w;
        }
        __syncthreads();

        // Gather fragments
        uint32_t af[NSLICE][4];
        const int r0 = wm * 16 + g;
#pragma unroll
        for (int s = 0; s < NSLICE; s++) {
            af[s][0] = As[s][r0 * 9 + tg];
            af[s][1] = As[s][(r0 + 8) * 9 + tg];
            af[s][2] = As[s][r0 * 9 + tg + 4];
            af[s][3] = As[s][(r0 + 8) * 9 + tg + 4];
        }
        uint32_t bf[NSLICE][5][2];
#pragma unroll
        for (int s = 0; s < NSLICE; s++)
#pragma unroll
            for (int nf = 0; nf < 5; nf++) {
                const int cb = wn * 40 + nf * 8 + g;
                bf[s][nf][0] = Bs[s][cb * 9 + tg];
                bf[s][nf][1] = Bs[s][cb * 9 + tg + 4];
            }

        // 15 slice pairs -> 5 diagonal accumulators (exact s32)
#pragma unroll
        for (int s = 0; s < NSLICE; s++)
#pragma unroll
            for (int t = 0; t + s < NSLICE; t++)
#pragma unroll
                for (int nf = 0; nf < 5; nf++)
                    mma_s8(acc[s + t][nf], af[s], bf[t][nf]);
        __syncthreads();
    }

    // Epilogue: fold diagonals (TwoSum, R14-proven), exact rescale, store.
    const float PW[NSLICE] = { 1.f, 0.0078125f, 6.103515625e-5f,
                               4.76837158203125e-7f,
                               3.7252902984619140625e-9f };
#pragma unroll
    for (int nf = 0; nf < 5; nf++) {
#pragma unroll
        for (int rr = 0; rr < 2; rr++) {
#pragma unroll
            for (int cc = 0; cc < 2; cc++) {
                const int reg = rr * 2 + cc;
                float s = 0.f, c = 0.f;
#pragma unroll
                for (int d = 0; d < NSLICE; d++) {
                    const float term =
                        __fmul_rn((float)acc[d][nf][reg], PW[d]);
                    const float t   = __fadd_rn(s, term);
                    const float bb  = __fsub_rn(t, s);
                    const float err = __fadd_rn(
                        __fsub_rn(s, __fsub_rn(t, bb)),
                        __fsub_rn(term, bb));
                    s = t;
                    c = __fadd_rn(c, err);
                }
                const int row = m0 + wm * 16 + g + 8 * rr;
                const int col = n0 + wn * 40 + nf * 8 + tg * 2 + cc;
                const float val = __fadd_rn(s, c);
                const float sc  = __fmul_rn(__ldg(su + row), __ldg(sv + col));
                C[(size_t)row * H + col] = __fmul_rn(val, sc);
            }
        }
    }
}

// ---------------------------------------------------------------------------
// SERIAL-FP32 GEMM (layer 2) — strict ascending-k fp32 FMA chain from 0 per
// output (bit-exact class, proven R9-R14). 8x10 micro-tile (BM=128, BN=160).
// ---------------------------------------------------------------------------
__global__ void __launch_bounds__(256)
gemm_nt_f32(const float* __restrict__ A, const float* __restrict__ Bw,
            float* __restrict__ C, int M, int N, int K)
{
    __shared__ float As[16][129];
    __shared__ float Bs[16][161];

    const int tid = threadIdx.x;
    const int tx  = tid & 15;
    const int ty  = tid >> 4;
    const int m0  = blockIdx.x * 128;
    const int n0  = blockIdx.y * 160;

    float acc[8][10];
#pragma unroll
    for (int i = 0; i < 8; i++)
#pragma unroll
        for (int j = 0; j < 10; j++) acc[i][j] = 0.f;

    for (int k0 = 0; k0 < K; k0 += 16) {
#pragma unroll
        for (int j = tid; j < 512; j += 256) {
            int row = j >> 2;
            int c4  = (j & 3) << 2;
            float4 v = *reinterpret_cast<const float4*>(
                A + (size_t)(m0 + row) * K + k0 + c4);
            As[c4 + 0][row] = v.x;
            As[c4 + 1][row] = v.y;
            As[c4 + 2][row] = v.z;
            As[c4 + 3][row] = v.w;
        }
#pragma unroll
        for (int j = tid; j < 640; j += 256) {
            int row = j >> 2;
            int c4  = (j & 3) << 2;
            float4 v = *reinterpret_cast<const float4*>(
                Bw + (size_t)(n0 + row) * K + k0 + c4);
            Bs[c4 + 0][row] = v.x;
            Bs[c4 + 1][row] = v.y;
            Bs[c4 + 2][row] = v.z;
            Bs[c4 + 3][row] = v.w;
        }
        __syncthreads();

#pragma unroll
        for (int kk = 0; kk < 16; kk++) {   // strict ascending-k chain
            float a[8], b[10];
#pragma unroll
            for (int i = 0; i < 8; i++) a[i] = As[kk][ty * 8 + i];
#pragma unroll
            for (int j = 0; j < 10; j++) b[j] = Bs[kk][tx * 10 + j];
#pragma unroll
            for (int i = 0; i < 8; i++)
#pragma unroll
                for (int j = 0; j < 10; j++)
                    acc[i][j] = fmaf(a[i], b[j], acc[i][j]);
        }
        __syncthreads();
    }

#pragma unroll
    for (int i = 0; i < 8; i++) {
        const int r = m0 + ty * 8 + i;
#pragma unroll
        for (int j = 0; j < 10; j++)
            C[(size_t)r * N + n0 + tx * 10 + j] = acc[i][j];
    }
}

// ---------------------------------------------------------------------------
// Skinny exact-dot GEMM (layer 3) via fp32 Dot2 — proven exact (R12-R14).
// ---------------------------------------------------------------------------
__global__ void __launch_bounds__(640)
gemm3_df32(const float* __restrict__ A, const float* __restrict__ W3,
           float* __restrict__ Cz)
{
    __shared__ float As[64][81];
    const int tid  = threadIdx.x;
    const int r    = tid & 63;
    const int o    = tid >> 6;          // 0..9
    const int row0 = blockIdx.x * 64;

    float s = 0.f, c = 0.f;
    for (int k0 = 0; k0 < 800; k0 += 80) {
        for (int j = tid; j < 1280; j += 640) {
            int rr = j / 20;
            int cc = (j % 20) * 4;
            float4 v = *reinterpret_cast<const float4*>(
                A + (size_t)(row0 + rr) * 800 + k0 + cc);
            As[rr][cc + 0] = v.x;
            As[rr][cc + 1] = v.y;
            As[rr][cc + 2] = v.z;
            As[rr][cc + 3] = v.w;
        }
        __syncthreads();
        const float* w = W3 + (size_t)o * 800 + k0;
#pragma unroll
        for (int k = 0; k < 80; k++) {
            const float a = As[r][k];
            const float b = __ldg(w + k);
            const float p  = __fmul_rn(a, b);
            const float ep = __fmaf_rn(a, b, -p);
            const float t   = __fadd_rn(s, p);
            const float bb  = __fsub_rn(t, s);
            const float err = __fadd_rn(
                __fsub_rn(s, __fsub_rn(t, bb)),
                __fsub_rn(p, bb));
            s = t;
            c = __fadd_rn(c, __fadd_rn(err, ep));
        }
        __syncthreads();
    }
    Cz[(size_t)(row0 + r) * OUT + o] = __fadd_rn(s, c);
}

// ---------------------------------------------------------------------------
// LIF scans — EXACT associations proven in R9-R14 (rel_err = 0). Do not change.
// ---------------------------------------------------------------------------
template <int ORDER>
__global__ void __launch_bounds__(256)
scan_hidden(const float* __restrict__ z, const float* __restrict__ bias,
            const float* __restrict__ thr, float* __restrict__ spk_out)
{
    const int idx = blockIdx.x * blockDim.x + threadIdx.x;
    if (idx >= BH) return;
    const int h = idx % H;
    const float bv = bias[h];
    const float tv = thr[h];
    float m = 0.f;
#pragma unroll
    for (int t = 0; t < T; t++) {
        const float zv = z[(size_t)t * BH + idx];
        float mnew;
        if (ORDER == 1) {
            const float xt = __fadd_rn(zv, bv);
            mnew = __fadd_rn(__fmul_rn(BETA, m), xt);
        } else {
            mnew = __fadd_rn(__fadd_rn(__fmul_rn(BETA, m), zv), bv);
        }
        const bool fire = (mnew > tv);
        spk_out[(size_t)t * BH + idx] = fire ? 1.f : 0.f;
        m = fire ? 0.f : mnew;
    }
}

__global__ void __launch_bounds__(256)
scan_out(const float* __restrict__ z3, const float* __restrict__ b3,
         float* __restrict__ s3, float* __restrict__ sum_out)
{
    const int idx = blockIdx.x * blockDim.x + threadIdx.x;
    if (idx >= BO) return;
    const int o = idx % OUT;
    const float bv = b3[o];
    float m = 0.f, sum = 0.f;
#pragma unroll
    for (int t = 0; t < T; t++) {
        const float zv = z3[(size_t)t * BO + idx];
        const float mnew = __fadd_rn(__fadd_rn(__fmul_rn(BETA, m), zv), bv);
        const bool fire = (mnew > 1.0f);
        const float s = fire ? 1.f : 0.f;
        s3[(size_t)t * BO + idx] = s;
        sum = __fadd_rn(sum, s);
        m = fire ? 0.f : mnew;
    }
    sum_out[idx] = sum;
}

// ---------------------------------------------------------------------------
// kernel_launch — graph-capturable, allocation-free.
// Inputs: x, W1, b1, W2, b2, W3, b3, thresh1, thresh2
// Outputs: sum[512,10], s1r[50,512,800], s2r[50,512,800], s3r[50,512,10]
// ---------------------------------------------------------------------------
extern "C" void kernel_launch(void* const* d_in, const int* in_sizes, int n_in,
                              void* d_out, int out_size)
{
    const float* x    = (const float*)d_in[0];
    const float* W1   = (const float*)d_in[1];
    const float* b1   = (const float*)d_in[2];
    const float* W2   = (const float*)d_in[3];
    const float* b2   = (const float*)d_in[4];
    const float* W3   = (const float*)d_in[5];
    const float* b3   = (const float*)d_in[6];
    const float* thr1 = (const float*)d_in[7];
    const float* thr2 = (const float*)d_in[8];

    float* out     = (float*)d_out;
    float* out_sum = out;                                  // [512,10]
    float* s1      = out + (size_t)BO;                     // [50,512,800]
    float* s2      = s1 + (size_t)T * BH;                  // [50,512,800]
    float* s3      = s2 + (size_t)T * BH;                  // [50,512,10]

    void *px1, *pz2, *pz3, *psx, *psw, *psu, *psv;
    cudaGetSymbolAddress(&px1, g_x1);
    cudaGetSymbolAddress(&pz2, g_z2);
    cudaGetSymbolAddress(&pz3, g_z3);
    cudaGetSymbolAddress(&psx, g_sx);
    cudaGetSymbolAddress(&psw, g_sw);
    cudaGetSymbolAddress(&psu, g_su);
    cudaGetSymbolAddress(&psv, g_sv);

    // 1) Slice x and W1 into 5 int8 planes (exact; K zero-padded to 800)
    slice_rows<<<MROWS, 256>>>(x, (int8_t*)psx, (float*)psu, IN,
                               (size_t)MROWS * KPAD);
    slice_rows<<<H, 256>>>(W1, (int8_t*)psw, (float*)psv, IN,
                           (size_t)H * KPAD);

    // 2) x1 = exact-dot(x, W1^T) via s8 TENSOR-CORE mma (diagonal-combined)
    {
        dim3 grid(MROWS / 64, H / 80);
        gemm1_imma<<<grid, 256>>>((const int8_t*)psx, (const int8_t*)psw,
                                  (const float*)psu, (const float*)psv,
                                  (float*)px1);
    }
    // 3) layer-1 LIF scan -> spk1  [bit-exact]
    scan_hidden<1><<<(BH + 255) / 256, 256>>>((const float*)px1, b1, thr1, s1);

    // 4) z2 = serial-fp32(spk1 @ W2^T)  [bit-exact]
    {
        dim3 grid(MROWS / 128, H / 160);
        gemm_nt_f32<<<grid, 256>>>(s1, W2, (float*)pz2, MROWS, H, H);
    }
    // 5) layer-2 LIF scan -> spk2  [bit-exact]
    scan_hidden<2><<<(BH + 255) / 256, 256>>>((const float*)pz2, b2, thr2, s2);

    // 6) z3 = exact-dot(spk2, W3^T) — fp32 Dot2
    gemm3_df32<<<MROWS / 64, 640>>>(s2, W3, (float*)pz3);

    // 7) layer-3 LIF scan -> s3r + spike-count sum
    scan_out<<<(BO + 255) / 256, 256>>>((const float*)pz3, b3, s3, out_sum);
}

// round 16
// speedup vs baseline: 1.9972x; 1.1589x over previous
#include <cuda_runtime.h>
#include <cstdint>
#include <cstddef>

// Problem constants
constexpr int T   = 50;
constexpr int B   = 512;
constexpr int IN  = 784;
constexpr int KPAD = 800;           // slices padded to 800 (25 x k32 chunks)
constexpr int H   = 800;
constexpr int OUT = 10;
constexpr int MROWS = T * B;        // 25600
constexpr int BH    = B * H;        // 409600
constexpr int BO    = B * OUT;      // 5120

constexpr int NSLICE = 5;           // 7-bit slices per fp32
constexpr int NCHUNK = KPAD / 32;   // 25

#define BETA 0.95f

// Scratch (static device globals; no runtime allocation)
__device__ float  g_x1[(size_t)T * BH];                  // x @ W1^T   (82 MB)
__device__ float  g_z2[(size_t)T * BH];                  // spk1 @ W2^T(82 MB)
__device__ float  g_z3[(size_t)T * BO];                  // spk2 @ W3^T(1 MB)
__device__ int8_t g_sx[(size_t)NSLICE * MROWS * KPAD];   // x slices (102 MB)
__device__ int8_t g_sw[(size_t)NSLICE * H * KPAD];       // W1 slices (3.2 MB)
__device__ float  g_su[MROWS];                           // per-row scale 2^(e-6)
__device__ float  g_sv[H];

// ---------------------------------------------------------------------------
// Row slicing (R14/R15-PROVEN exact): m = row max|x|, e = ilogb(m)+1;
// slice s = rint(resid / 2^(e-6-7s)), |slice| <= 64; exact FMA residual.
// K zero-padded to KPAD.
// ---------------------------------------------------------------------------
__global__ void __launch_bounds__(256)
slice_rows(const float* __restrict__ X, int8_t* __restrict__ S,
           float* __restrict__ scale, int cols, size_t plane)
{
    const int row = blockIdx.x;
    const int tid = threadIdx.x;
    const float* xr = X + (size_t)row * cols;

    __shared__ float red[256];
    float m = 0.f;
    for (int k = tid; k < cols; k += 256) m = fmaxf(m, fabsf(xr[k]));
    red[tid] = m;
    __syncthreads();
    for (int w = 128; w > 0; w >>= 1) {
        if (tid < w) red[tid] = fmaxf(red[tid], red[tid + w]);
        __syncthreads();
    }
    m = red[0];
    const int e = (m > 0.f) ? (ilogbf(m) + 1) : 0;
    if (tid == 0) scale[row] = ldexpf(1.f, e - 6);

    const float u0   = ldexpf(1.f, e - 6);
    const float inv0 = ldexpf(1.f, 6 - e);

    for (int k = tid; k < cols; k += 256) {
        float r  = xr[k];
        float uu = u0, ii = inv0;
#pragma unroll
        for (int s = 0; s < NSLICE; s++) {
            const float q = rintf(__fmul_rn(r, ii));   // |q| <= 64
            S[(size_t)s * plane + (size_t)row * KPAD + k] = (int8_t)(int)q;
            r  = __fmaf_rn(-q, uu, r);                 // exact residual
            uu = __fmul_rn(uu, 0.0078125f);            // * 2^-7 (exact)
            ii = __fmul_rn(ii, 128.f);
        }
    }
    for (int k = cols + tid; k < KPAD; k += 256)
#pragma unroll
        for (int s = 0; s < NSLICE; s++)
            S[(size_t)s * plane + (size_t)row * KPAD + k] = 0;
}

// ---------------------------------------------------------------------------
// Layer-1 EXACT-DOT GEMM on tensor cores (s8 mma, exact s32) — R15 math,
// rescheduled: 16x16 warp tile (acc 40 regs), 2 CTAs/SM, double-buffered
// smem with register prefetch, 1 sync per k-chunk.
// Block 64x32, 8 warps (4m x 2n). Diagonal-shared accumulators:
// |G_d| <= 5*784*64^2 = 16.06M < 2^24 so (float)G_d exact; TwoSum fold of 5
// diagonal terms; exact power-of-2 rescale. Identical numerics to R15.
// ---------------------------------------------------------------------------
__device__ __forceinline__ void mma_s8(int* d, const uint32_t* a,
                                       const uint32_t* b)
{
    asm volatile(
        "mma.sync.aligned.m16n8k32.row.col.s32.s8.s8.s32 "
        "{%0,%1,%2,%3}, {%4,%5,%6,%7}, {%8,%9}, {%0,%1,%2,%3};"
        : "+r"(d[0]), "+r"(d[1]), "+r"(d[2]), "+r"(d[3])
        : "r"(a[0]), "r"(a[1]), "r"(a[2]), "r"(a[3]),
          "r"(b[0]), "r"(b[1]));
}

__global__ void __launch_bounds__(256, 2)
gemm1_imma(const int8_t* __restrict__ SX, const int8_t* __restrict__ SW,
           const float* __restrict__ su, const float* __restrict__ sv,
           float* __restrict__ C)
{
    // Double-buffered smem tiles: [buf][slice][row * 9 u32]
    __shared__ uint32_t As[2][NSLICE][64 * 9];   // 23.0 KB
    __shared__ uint32_t Bs[2][NSLICE][32 * 9];   // 11.5 KB

    const int tid  = threadIdx.x;
    const int warp = tid >> 5;
    const int lane = tid & 31;
    const int g    = lane >> 2;     // 0..7
    const int tg   = lane & 3;      // 0..3
    const int wm   = warp >> 1;     // 0..3  (16 rows each)
    const int wn   = warp & 1;      // 0..1  (16 cols each)
    const int m0   = blockIdx.x * 64;
    const int n0   = blockIdx.y * 32;

    int acc[NSLICE][2][4];          // [diagonal][n-frag][reg], exact s32
#pragma unroll
    for (int d = 0; d < NSLICE; d++)
#pragma unroll
        for (int nf = 0; nf < 2; nf++)
#pragma unroll
            for (int r = 0; r < 4; r++) acc[d][nf][r] = 0;

    // --- prefetch helpers: A = 640 uint4 (<=3/thread), B = 320 (<=2/thread)
    auto ldA = [&](int k0, uint4* ra) {
#pragma unroll
        for (int u = 0; u < 3; u++) {
            const int idx = tid + u * 256;
            if (idx < 640) {
                const int s   = idx >> 7;
                const int rem = idx & 127;
                const int row = rem >> 1;
                const int q   = rem & 1;
                ra[u] = *reinterpret_cast<const uint4*>(
                    SX + (size_t)s * ((size_t)MROWS * KPAD)
                       + (size_t)(m0 + row) * KPAD + k0 + q * 16);
            }
        }
    };
    auto ldB = [&](int k0, uint4* rb) {
#pragma unroll
        for (int u = 0; u < 2; u++) {
            const int idx = tid + u * 256;
            if (idx < 320) {
                const int s   = idx >> 6;
                const int rem = idx & 63;
                const int row = rem >> 1;
                const int q   = rem & 1;
                rb[u] = *reinterpret_cast<const uint4*>(
                    SW + (size_t)s * ((size_t)H * KPAD)
                       + (size_t)(n0 + row) * KPAD + k0 + q * 16);
            }
        }
    };
    auto stA = [&](int p, const uint4* ra) {
#pragma unroll
        for (int u = 0; u < 3; u++) {
            const int idx = tid + u * 256;
            if (idx < 640) {
                const int s   = idx >> 7;
                const int rem = idx & 127;
                const int row = rem >> 1;
                const int q   = rem & 1;
                uint32_t* dst = &As[p][s][row * 9 + q * 4];
                dst[0] = ra[u].x; dst[1] = ra[u].y;
                dst[2] = ra[u].z; dst[3] = ra[u].w;
            }
        }
    };
    auto stB = [&](int p, const uint4* rb) {
#pragma unroll
        for (int u = 0; u < 2; u++) {
            const int idx = tid + u * 256;
            if (idx < 320) {
                const int s   = idx >> 6;
                const int rem = idx & 63;
                const int row = rem >> 1;
                const int q   = rem & 1;
                uint32_t* dst = &Bs[p][s][row * 9 + q * 4];
                dst[0] = rb[u].x; dst[1] = rb[u].y;
                dst[2] = rb[u].z; dst[3] = rb[u].w;
            }
        }
    };

    uint4 ra[3], rb[2];
    ldA(0, ra); ldB(0, rb);
    stA(0, ra); stB(0, rb);
    __syncthreads();

    int p = 0;
    for (int kc = 0; kc < NCHUNK; kc++) {
        // Prefetch next chunk into registers (overlaps with compute below)
        if (kc + 1 < NCHUNK) {
            ldA((kc + 1) * 32, ra);
            ldB((kc + 1) * 32, rb);
        }

        // Gather fragments from buf p
        uint32_t af[NSLICE][4];
        const int r0 = wm * 16 + g;
#pragma unroll
        for (int s = 0; s < NSLICE; s++) {
            af[s][0] = As[p][s][r0 * 9 + tg];
            af[s][1] = As[p][s][(r0 + 8) * 9 + tg];
            af[s][2] = As[p][s][r0 * 9 + tg + 4];
            af[s][3] = As[p][s][(r0 + 8) * 9 + tg + 4];
        }
        uint32_t bf[NSLICE][2][2];
#pragma unroll
        for (int s = 0; s < NSLICE; s++)
#pragma unroll
            for (int nf = 0; nf < 2; nf++) {
                const int cb = wn * 16 + nf * 8 + g;
                bf[s][nf][0] = Bs[p][s][cb * 9 + tg];
                bf[s][nf][1] = Bs[p][s][cb * 9 + tg + 4];
            }

        // 15 slice pairs -> 5 diagonal accumulators (exact s32)
#pragma unroll
        for (int s = 0; s < NSLICE; s++)
#pragma unroll
            for (int t = 0; t + s < NSLICE; t++)
#pragma unroll
                for (int nf = 0; nf < 2; nf++)
                    mma_s8(acc[s + t][nf], af[s], bf[t][nf]);

        // Store prefetched chunk into the other buffer, flip
        if (kc + 1 < NCHUNK) {
            stA(1 - p, ra);
            stB(1 - p, rb);
        }
        __syncthreads();
        p ^= 1;
    }

    // Epilogue: fold diagonals (TwoSum, proven), exact rescale, store.
    const float PW[NSLICE] = { 1.f, 0.0078125f, 6.103515625e-5f,
                               4.76837158203125e-7f,
                               3.7252902984619140625e-9f };
#pragma unroll
    for (int nf = 0; nf < 2; nf++) {
#pragma unroll
        for (int rr = 0; rr < 2; rr++) {
#pragma unroll
            for (int cc = 0; cc < 2; cc++) {
                const int reg = rr * 2 + cc;
                float s = 0.f, c = 0.f;
#pragma unroll
                for (int d = 0; d < NSLICE; d++) {
                    const float term =
                        __fmul_rn((float)acc[d][nf][reg], PW[d]);
                    const float t   = __fadd_rn(s, term);
                    const float bb  = __fsub_rn(t, s);
                    const float err = __fadd_rn(
                        __fsub_rn(s, __fsub_rn(t, bb)),
                        __fsub_rn(term, bb));
                    s = t;
                    c = __fadd_rn(c, err);
                }
                const int row = m0 + wm * 16 + g + 8 * rr;
                const int col = n0 + wn * 16 + nf * 8 + tg * 2 + cc;
                const float val = __fadd_rn(s, c);
                const float sc  = __fmul_rn(__ldg(su + row), __ldg(sv + col));
                C[(size_t)row * H + col] = __fmul_rn(val, sc);
            }
        }
    }
}

// ---------------------------------------------------------------------------
// SERIAL-FP32 GEMM (layer 2) — strict ascending-k fp32 FMA chain from 0 per
// output (bit-exact class, proven R9-R15). 8x10 micro-tile (BM=128, BN=160).
// ---------------------------------------------------------------------------
__global__ void __launch_bounds__(256)
gemm_nt_f32(const float* __restrict__ A, const float* __restrict__ Bw,
            float* __restrict__ C, int M, int N, int K)
{
    __shared__ float As[16][129];
    __shared__ float Bs[16][161];

    const int tid = threadIdx.x;
    const int tx  = tid & 15;
    const int ty  = tid >> 4;
    const int m0  = blockIdx.x * 128;
    const int n0  = blockIdx.y * 160;

    float acc[8][10];
#pragma unroll
    for (int i = 0; i < 8; i++)
#pragma unroll
        for (int j = 0; j < 10; j++) acc[i][j] = 0.f;

    for (int k0 = 0; k0 < K; k0 += 16) {
#pragma unroll
        for (int j = tid; j < 512; j += 256) {
            int row = j >> 2;
            int c4  = (j & 3) << 2;
            float4 v = *reinterpret_cast<const float4*>(
                A + (size_t)(m0 + row) * K + k0 + c4);
            As[c4 + 0][row] = v.x;
            As[c4 + 1][row] = v.y;
            As[c4 + 2][row] = v.z;
            As[c4 + 3][row] = v.w;
        }
#pragma unroll
        for (int j = tid; j < 640; j += 256) {
            int row = j >> 2;
            int c4  = (j & 3) << 2;
            float4 v = *reinterpret_cast<const float4*>(
                Bw + (size_t)(n0 + row) * K + k0 + c4);
            Bs[c4 + 0][row] = v.x;
            Bs[c4 + 1][row] = v.y;
            Bs[c4 + 2][row] = v.z;
            Bs[c4 + 3][row] = v.w;
        }
        __syncthreads();

#pragma unroll
        for (int kk = 0; kk < 16; kk++) {   // strict ascending-k chain
            float a[8], b[10];
#pragma unroll
            for (int i = 0; i < 8; i++) a[i] = As[kk][ty * 8 + i];
#pragma unroll
            for (int j = 0; j < 10; j++) b[j] = Bs[kk][tx * 10 + j];
#pragma unroll
            for (int i = 0; i < 8; i++)
#pragma unroll
                for (int j = 0; j < 10; j++)
                    acc[i][j] = fmaf(a[i], b[j], acc[i][j]);
        }
        __syncthreads();
    }

#pragma unroll
    for (int i = 0; i < 8; i++) {
        const int r = m0 + ty * 8 + i;
#pragma unroll
        for (int j = 0; j < 10; j++)
            C[(size_t)r * N + n0 + tx * 10 + j] = acc[i][j];
    }
}

// ---------------------------------------------------------------------------
// Skinny exact-dot GEMM (layer 3) via fp32 Dot2 — proven exact (R12-R15).
// ---------------------------------------------------------------------------
__global__ void __launch_bounds__(640)
gemm3_df32(const float* __restrict__ A, const float* __restrict__ W3,
           float* __restrict__ Cz)
{
    __shared__ float As[64][81];
    const int tid  = threadIdx.x;
    const int r    = tid & 63;
    const int o    = tid >> 6;          // 0..9
    const int row0 = blockIdx.x * 64;

    float s = 0.f, c = 0.f;
    for (int k0 = 0; k0 < 800; k0 += 80) {
        for (int j = tid; j < 1280; j += 640) {
            int rr = j / 20;
            int cc = (j % 20) * 4;
            float4 v = *reinterpret_cast<const float4*>(
                A + (size_t)(row0 + rr) * 800 + k0 + cc);
            As[rr][cc + 0] = v.x;
            As[rr][cc + 1] = v.y;
            As[rr][cc + 2] = v.z;
            As[rr][cc + 3] = v.w;
        }
        __syncthreads();
        const float* w = W3 + (size_t)o * 800 + k0;
#pragma unroll
        for (int k = 0; k < 80; k++) {
            const float a = As[r][k];
            const float b = __ldg(w + k);
            const float p  = __fmul_rn(a, b);
            const float ep = __fmaf_rn(a, b, -p);
            const float t   = __fadd_rn(s, p);
            const float bb  = __fsub_rn(t, s);
            const float err = __fadd_rn(
                __fsub_rn(s, __fsub_rn(t, bb)),
                __fsub_rn(p, bb));
            s = t;
            c = __fadd_rn(c, __fadd_rn(err, ep));
        }
        __syncthreads();
    }
    Cz[(size_t)(row0 + r) * OUT + o] = __fadd_rn(s, c);
}

// ---------------------------------------------------------------------------
// LIF scans — EXACT associations proven in R9-R15 (rel_err = 0). Do not change.
// ---------------------------------------------------------------------------
template <int ORDER>
__global__ void __launch_bounds__(256)
scan_hidden(const float* __restrict__ z, const float* __restrict__ bias,
            const float* __restrict__ thr, float* __restrict__ spk_out)
{
    const int idx = blockIdx.x * blockDim.x + threadIdx.x;
    if (idx >= BH) return;
    const int h = idx % H;
    const float bv = bias[h];
    const float tv = thr[h];
    float m = 0.f;
#pragma unroll
    for (int t = 0; t < T; t++) {
        const float zv = z[(size_t)t * BH + idx];
        float mnew;
        if (ORDER == 1) {
            const float xt = __fadd_rn(zv, bv);
            mnew = __fadd_rn(__fmul_rn(BETA, m), xt);
        } else {
            mnew = __fadd_rn(__fadd_rn(__fmul_rn(BETA, m), zv), bv);
        }
        const bool fire = (mnew > tv);
        spk_out[(size_t)t * BH + idx] = fire ? 1.f : 0.f;
        m = fire ? 0.f : mnew;
    }
}

__global__ void __launch_bounds__(256)
scan_out(const float* __restrict__ z3, const float* __restrict__ b3,
         float* __restrict__ s3, float* __restrict__ sum_out)
{
    const int idx = blockIdx.x * blockDim.x + threadIdx.x;
    if (idx >= BO) return;
    const int o = idx % OUT;
    const float bv = b3[o];
    float m = 0.f, sum = 0.f;
#pragma unroll
    for (int t = 0; t < T; t++) {
        const float zv = z3[(size_t)t * BO + idx];
        const float mnew = __fadd_rn(__fadd_rn(__fmul_rn(BETA, m), zv), bv);
        const bool fire = (mnew > 1.0f);
        const float s = fire ? 1.f : 0.f;
        s3[(size_t)t * BO + idx] = s;
        sum = __fadd_rn(sum, s);
        m = fire ? 0.f : mnew;
    }
    sum_out[idx] = sum;
}

// ---------------------------------------------------------------------------
// kernel_launch — graph-capturable, allocation-free.
// Inputs: x, W1, b1, W2, b2, W3, b3, thresh1, thresh2
// Outputs: sum[512,10], s1r[50,512,800], s2r[50,512,800], s3r[50,512,10]
// ---------------------------------------------------------------------------
extern "C" void kernel_launch(void* const* d_in, const int* in_sizes, int n_in,
                              void* d_out, int out_size)
{
    const float* x    = (const float*)d_in[0];
    const float* W1   = (const float*)d_in[1];
    const float* b1   = (const float*)d_in[2];
    const float* W2   = (const float*)d_in[3];
    const float* b2   = (const float*)d_in[4];
    const float* W3   = (const float*)d_in[5];
    const float* b3   = (const float*)d_in[6];
    const float* thr1 = (const float*)d_in[7];
    const float* thr2 = (const float*)d_in[8];

    float* out     = (float*)d_out;
    float* out_sum = out;                                  // [512,10]
    float* s1      = out + (size_t)BO;                     // [50,512,800]
    float* s2      = s1 + (size_t)T * BH;                  // [50,512,800]
    float* s3      = s2 + (size_t)T * BH;                  // [50,512,10]

    void *px1, *pz2, *pz3, *psx, *psw, *psu, *psv;
    cudaGetSymbolAddress(&px1, g_x1);
    cudaGetSymbolAddress(&pz2, g_z2);
    cudaGetSymbolAddress(&pz3, g_z3);
    cudaGetSymbolAddress(&psx, g_sx);
    cudaGetSymbolAddress(&psw, g_sw);
    cudaGetSymbolAddress(&psu, g_su);
    cudaGetSymbolAddress(&psv, g_sv);

    // 1) Slice x and W1 into 5 int8 planes (exact; K zero-padded to 800)
    slice_rows<<<MROWS, 256>>>(x, (int8_t*)psx, (float*)psu, IN,
                               (size_t)MROWS * KPAD);
    slice_rows<<<H, 256>>>(W1, (int8_t*)psw, (float*)psv, IN,
                           (size_t)H * KPAD);

    // 2) x1 = exact-dot(x, W1^T) via s8 tensor-core mma (double-buffered)
    {
        dim3 grid(MROWS / 64, H / 32);
        gemm1_imma<<<grid, 256>>>((const int8_t*)psx, (const int8_t*)psw,
                                  (const float*)psu, (const float*)psv,
                                  (float*)px1);
    }
    // 3) layer-1 LIF scan -> spk1  [bit-exact]
    scan_hidden<1><<<(BH + 255) / 256, 256>>>((const float*)px1, b1, thr1, s1);

    // 4) z2 = serial-fp32(spk1 @ W2^T)  [bit-exact]
    {
        dim3 grid(MROWS / 128, H / 160);
        gemm_nt_f32<<<grid, 256>>>(s1, W2, (float*)pz2, MROWS, H, H);
    }
    // 5) layer-2 LIF scan -> spk2  [bit-exact]
    scan_hidden<2><<<(BH + 255) / 256, 256>>>((const float*)pz2, b2, thr2, s2);

    // 6) z3 = exact-dot(spk2, W3^T) — fp32 Dot2
    gemm3_df32<<<MROWS / 64, 640>>>(s2, W3, (float*)pz3);

    // 7) layer-3 LIF scan -> s3r + spike-count sum
    scan_out<<<(BO + 255) / 256, 256>>>((const float*)pz3, b3, s3, out_sum);
}